// round 17
// baseline (speedup 1.0000x reference)
#include <cuda_runtime.h>
#include <cuda_bf16.h>
#include <cuda_fp8.h>
#include <float.h>
#include <stdint.h>

#define NQ      2048
#define DIMS    128
#define MTRAIN  100000
#define KNB     16
#define NC      10
#define NSPLIT  9
#define SPLIT   11136          // 87*128: splits 0-7 chunk-aligned
#define QTILE   128
#define CHUNK   128
#define QCAP    48
#define KEEP    24             // per-split kept candidates (widened for fp8 noise)
#define NCAND   (NSPLIT*KEEP)  // 216
#define T0      100.0f

// smem map (bytes)
#define SA_OFF  0                     // 16KB A tile (128 x 128B fp8)
#define SB(s)   (16384 + (s)*16384)   // 2 x 16KB B tiles
#define T2_OFF  49152                 // 2 x 128 floats
#define QV_OFF  50176                 // 2 x 128 x 48 floats = 49152
#define QI_OFF  99328                 // 49152
#define CNT_OFF 148480                // 256 ints
#define LV_OFF  149504                // 24 x 128 floats = 12288
#define LI_OFF  161792                // 12288
#define VMX_OFF 174080                // 128 floats
#define SMEM_TOTAL 174592

// padded; pad rows POISONED (t2=1e30, train=0) -> produce needs no bounds checks
__device__ float   g_t2[MTRAIN + 128];
__device__ float   g_x2[NQ];
__device__ uint8_t g_train_q8[(size_t)(MTRAIN + 128) * DIMS];
__device__ uint8_t g_x_q8[NQ * DIMS];
__device__ float   g_topd[NQ * NCAND];
__device__ int     g_topi[NQ * NCAND];

__device__ __forceinline__ uint32_t smem_u32(const void* p) {
    uint32_t a;
    asm("{ .reg .u64 t; cvta.to.shared.u64 t, %1; cvt.u32.u64 %0, t; }" : "=r"(a) : "l"(p));
    return a;
}
__device__ __forceinline__ void cpa16(uint32_t dst, const void* src) {
    asm volatile("cp.async.cg.shared.global [%0], [%1], 16;" :: "r"(dst), "l"(src));
}
#define CP_COMMIT() asm volatile("cp.async.commit_group;" ::: "memory")
#define CP_WAIT0()  asm volatile("cp.async.wait_group 0;" ::: "memory")

// 128B-row swizzle: XOR 16B-slot bits[4:7) with row%8
__device__ __forceinline__ uint32_t swz8(uint32_t off) {
    return off ^ ((off >> 3) & 0x70u);
}
__device__ __forceinline__ uint8_t q8(float v) {
    return (uint8_t)__nv_cvt_float_to_fp8(v, __NV_SATFINITE, __NV_E4M3);
}

// -------- kernel 1: norms + e4m3 quantization + poisoned pad --------
__global__ void prep_kernel(const float* __restrict__ x, const float* __restrict__ train) {
    int warp = (blockIdx.x * blockDim.x + threadIdx.x) >> 5;
    int lane = threadIdx.x & 31;
    if (warp >= MTRAIN + NQ + 128) return;

    if (warp >= MTRAIN + NQ) {                 // pad rows: poison
        int pr = warp - MTRAIN - NQ;
        ((uint32_t*)(g_train_q8 + (size_t)(MTRAIN + pr) * DIMS))[lane] = 0u;
        if (lane == 0) g_t2[MTRAIN + pr] = 1e30f;
        return;
    }

    const float* src; uint8_t* dq; float* t2dst;
    if (warp < MTRAIN) {
        src = train + (size_t)warp * DIMS;
        dq = g_train_q8 + (size_t)warp * DIMS;
        t2dst = g_t2 + warp;
    } else {
        int q = warp - MTRAIN;
        src = x + (size_t)q * DIMS;
        dq = g_x_q8 + (size_t)q * DIMS;
        t2dst = g_x2 + q;
    }
    float4 v = ((const float4*)src)[lane];
    uint32_t pk = (uint32_t)q8(v.x) | ((uint32_t)q8(v.y) << 8)
                | ((uint32_t)q8(v.z) << 16) | ((uint32_t)q8(v.w) << 24);
    ((uint32_t*)dq)[lane] = pk;
    float s = v.x*v.x + v.y*v.y + v.z*v.z + v.w*v.w;
    #pragma unroll
    for (int o = 16; o > 0; o >>= 1) s += __shfl_down_sync(0xffffffffu, s, o);
    if (lane == 0) *t2dst = s;
}

// per-query top-KEEP insert (scanner-owned, stride-128 layout)
__device__ __forceinline__ void topk_ins(float* lv, int* li, int t,
                                         float sc, int gc, float& vmax, int& maxslot) {
    lv[maxslot * 128 + t] = sc;
    li[maxslot * 128 + t] = gc;
    float nm = lv[t]; int np = 0;
    #pragma unroll
    for (int j = 1; j < KEEP; j++) {
        float tj = lv[j * 128 + t];
        if (tj > nm) { nm = tj; np = j; }
    }
    vmax = nm; maxslot = np;
}

// -------- kernel 2: fp8 QMMA approx GEMM + threshold-filtered sparse top-24 --------
__global__ __launch_bounds__(256, 1) void knn_kernel() {
    extern __shared__ char sm[];
    const uint32_t sb = smem_u32(sm);
    float* t2r  = (float*)(sm + T2_OFF);
    float* qv   = (float*)(sm + QV_OFF);
    int*   qi   = (int*)(sm + QI_OFF);
    int*   cnts = (int*)(sm + CNT_OFF);
    float* lv   = (float*)(sm + LV_OFF);
    int*   li   = (int*)(sm + LI_OFF);
    float* vmx  = (float*)(sm + VMX_OFF);

    const int tid = threadIdx.x;
    const int wid = tid >> 5;
    const int lane = tid & 31;
    const int split = blockIdx.x;
    const int qt    = blockIdx.y;
    const int split_start = split * SPLIT;
    const int split_end   = min(split_start + SPLIT, MTRAIN);
    const int nch = (split_end - split_start + CHUNK - 1) / CHUNK;

    const int m0 = (wid >> 2) * 64;
    const int n0 = (wid & 3) * 32;
    const int frow  = lane & 15;               // ldmatrix row-within-16
    const int fbyte = (lane >> 4) * 16;        // 16B half select
    const int tq = lane >> 2, tc = lane & 3;

    // prologue: A (1024 slots) + B(0) (1024 slots) + t2(0)
    #pragma unroll
    for (int i = 0; i < 4; i++) {
        int e = tid + i * 256;
        int row = e >> 3, c16 = e & 7;
        uint32_t off = swz8((uint32_t)(row * 128 + c16 * 16));
        cpa16(sb + SA_OFF + off, g_x_q8 + (size_t)(qt * QTILE + row) * 128 + c16 * 16);
        cpa16(sb + SB(0) + off, g_train_q8 + (size_t)(split_start + row) * 128 + c16 * 16);
    }
    if (tid < 32) cpa16(sb + T2_OFF + tid * 16, (const char*)(g_t2 + split_start) + tid * 16);
    CP_COMMIT();

    if (tid < 128) {
        #pragma unroll
        for (int j = 0; j < KEEP; j++) { lv[j * 128 + tid] = FLT_MAX; li[j * 128 + tid] = 0; }
        vmx[tid] = FLT_MAX;
    }
    cnts[tid] = 0;
    float vmax = FLT_MAX; int maxslot = 0;
    CP_WAIT0();
    __syncthreads();

    for (int ch = 0; ch < nch; ch++) {
        const int cb = split_start + ch * CHUNK;
        const int nx = ch + 1;
        const int s = ch & 1;
        const int cbuf = ch & 1;

        // prefetch B(ch+1) + t2(ch+1)  (unguarded; arrays padded + poisoned)
        if (nx < nch) {
            const int cbn = split_start + nx * CHUNK;
            #pragma unroll
            for (int i = 0; i < 4; i++) {
                int e = tid + i * 256;
                int row = e >> 3, c16 = e & 7;
                cpa16(sb + SB(nx & 1) + swz8((uint32_t)(row * 128 + c16 * 16)),
                      g_train_q8 + (size_t)(cbn + row) * 128 + c16 * 16);
            }
            if (tid < 32) cpa16(sb + T2_OFF + (nx & 1) * 512 + tid * 16,
                                (const char*)(g_t2 + cbn) + tid * 16);
            CP_COMMIT();
        }

        float acc[16][4];
        #pragma unroll
        for (int i = 0; i < 16; i++)
            #pragma unroll
            for (int j = 0; j < 4; j++) acc[i][j] = 0.f;

        const uint32_t sa = sb + SA_OFF, sbB = sb + SB(s);

        // MMA k-loop: 4 k-steps of 32 e4m3 (R10-proven byte addressing)
        #pragma unroll
        for (int kk = 0; kk < 4; kk++) {
            uint32_t a[4][4], b[4][2];
            #pragma unroll
            for (int i = 0; i < 4; i++) {
                uint32_t off = swz8((uint32_t)((m0 + i * 16 + frow) * 128 + kk * 32 + fbyte));
                asm volatile("ldmatrix.sync.aligned.m8n8.x4.shared.b16 {%0,%1,%2,%3}, [%4];"
                    : "=r"(a[i][0]), "=r"(a[i][1]), "=r"(a[i][2]), "=r"(a[i][3])
                    : "r"(sa + off));
            }
            #pragma unroll
            for (int j2 = 0; j2 < 2; j2++) {
                uint32_t r0, r1, r2, r3;
                uint32_t off = swz8((uint32_t)((n0 + j2 * 16 + frow) * 128 + kk * 32 + fbyte));
                asm volatile("ldmatrix.sync.aligned.m8n8.x4.shared.b16 {%0,%1,%2,%3}, [%4];"
                    : "=r"(r0), "=r"(r1), "=r"(r2), "=r"(r3) : "r"(sbB + off));
                b[j2*2][0] = r0;   b[j2*2][1] = r2;
                b[j2*2+1][0] = r1; b[j2*2+1][1] = r3;
            }
            #pragma unroll
            for (int i = 0; i < 4; i++)
                #pragma unroll
                for (int j = 0; j < 4; j++) {
                    float* d = acc[i * 4 + j];
                    asm volatile("mma.sync.aligned.m16n8k32.row.col.f32.e4m3.e4m3.f32 "
                        "{%0,%1,%2,%3}, {%4,%5,%6,%7}, {%8,%9}, {%0,%1,%2,%3};"
                        : "+f"(d[0]), "+f"(d[1]), "+f"(d[2]), "+f"(d[3])
                        : "r"(a[i][0]), "r"(a[i][1]), "r"(a[i][2]), "r"(a[i][3]),
                          "r"(b[j][0]), "r"(b[j][1]));
                }
        }

        // ---- produce: threshold-filter scores, append survivors (branchless bounds) ----
        {
            float thrA[4], thrB[4];
            #pragma unroll
            for (int i = 0; i < 4; i++) {
                thrA[i] = fminf(vmx[m0 + i * 16 + tq], T0);
                thrB[i] = fminf(vmx[m0 + i * 16 + tq + 8], T0);
            }
            const float* t2c = t2r + (ch & 1) * 128;
            #pragma unroll
            for (int j = 0; j < 4; j++) {
                int c2 = (n0 >> 1) + j * 4 + tc;
                int c0 = 2 * c2;
                float t20 = t2c[c0], t21 = t2c[c0 + 1];
                int g0 = cb + c0, g1 = g0 + 1;
                #pragma unroll
                for (int i = 0; i < 4; i++) {
                    const float* d = acc[i * 4 + j];
                    int qa = m0 + i * 16 + tq, qb = qa + 8;
                    float s00 = fmaf(-2.f, d[0], t20);
                    float s01 = fmaf(-2.f, d[1], t21);
                    float s10 = fmaf(-2.f, d[2], t20);
                    float s11 = fmaf(-2.f, d[3], t21);
                    if (s00 < thrA[i]) {
                        int sl = atomicAdd(&cnts[cbuf * 128 + qa], 1);
                        if (sl < QCAP) { qv[(cbuf*128+qa)*QCAP+sl] = s00; qi[(cbuf*128+qa)*QCAP+sl] = g0; }
                    }
                    if (s01 < thrA[i]) {
                        int sl = atomicAdd(&cnts[cbuf * 128 + qa], 1);
                        if (sl < QCAP) { qv[(cbuf*128+qa)*QCAP+sl] = s01; qi[(cbuf*128+qa)*QCAP+sl] = g1; }
                    }
                    if (s10 < thrB[i]) {
                        int sl = atomicAdd(&cnts[cbuf * 128 + qb], 1);
                        if (sl < QCAP) { qv[(cbuf*128+qb)*QCAP+sl] = s10; qi[(cbuf*128+qb)*QCAP+sl] = g0; }
                    }
                    if (s11 < thrB[i]) {
                        int sl = atomicAdd(&cnts[cbuf * 128 + qb], 1);
                        if (sl < QCAP) { qv[(cbuf*128+qb)*QCAP+sl] = s11; qi[(cbuf*128+qb)*QCAP+sl] = g1; }
                    }
                }
            }
        }

        // ---- drain previous chunk's queue (scanner t owns query t) ----
        {
            const int pb = cbuf ^ 1;
            if (tid < 128) {
                int n = min(cnts[pb * 128 + tid], QCAP);
                const float* qvb = qv + (pb * 128 + tid) * QCAP;
                const int*   qib = qi + (pb * 128 + tid) * QCAP;
                for (int k = 0; k < n; k++) {
                    float v = qvb[k];
                    if (v < vmax) topk_ins(lv, li, tid, v, qib[k], vmax, maxslot);
                }
                cnts[pb * 128 + tid] = 0;
                vmx[tid] = vmax;
            }
        }
        CP_WAIT0();
        __syncthreads();
    }

    // ---- tail: drain last chunk's queue ----
    {
        const int pb = (nch - 1) & 1;
        if (tid < 128) {
            int n = min(cnts[pb * 128 + tid], QCAP);
            const float* qvb = qv + (pb * 128 + tid) * QCAP;
            const int*   qib = qi + (pb * 128 + tid) * QCAP;
            for (int k = 0; k < n; k++) {
                float v = qvb[k];
                if (v < vmax) topk_ins(lv, li, tid, v, qib[k], vmax, maxslot);
            }
        }
    }
    __syncthreads();

    // dump per-(query,split) top-KEEP approx candidates
    if (tid < 128) {
        int q = qt * QTILE + tid;
        int base = (q * NSPLIT + split) * KEEP;
        #pragma unroll
        for (int j = 0; j < KEEP; j++) {
            g_topd[base + j] = lv[j * 128 + tid];
            g_topi[base + j] = li[j * 128 + tid];
        }
    }
}

// -------- kernel 3: merge 216 approx -> top-48 -> exact fp32 refine -> vote --------
__global__ void finalize_kernel(const float* __restrict__ x,
                                const float* __restrict__ train,
                                const int* __restrict__ labels,
                                float* __restrict__ pred_out,
                                float* __restrict__ proba_out) {
    __shared__ float xs[8][128];
    int warp = threadIdx.x >> 5, lane = threadIdx.x & 31;
    int q = blockIdx.x * 8 + warp;

    float cv[7]; int ci[7];
    const float* td = g_topd + (size_t)q * NCAND;
    const int*   ti = g_topi + (size_t)q * NCAND;
    #pragma unroll
    for (int t = 0; t < 7; t++) {
        int idx = lane + 32 * t;
        if (idx < NCAND) { cv[t] = td[idx]; ci[t] = ti[idx]; }
        else             { cv[t] = FLT_MAX; ci[t] = 0; }
    }

    // approx-top-48; round r winner kept by lane (r&31), slot (r>>5)
    int myidx0 = 0, myidx1 = 0;
    for (int r = 0; r < 48; r++) {
        float mv = cv[0]; int ms = 0;
        #pragma unroll
        for (int t = 1; t < 7; t++) if (cv[t] < mv) { mv = cv[t]; ms = t; }
        float rv = mv; int ridx = ci[0]; int rlane = lane;
        #pragma unroll
        for (int t = 0; t < 7; t++) if (t == ms) ridx = ci[t];
        #pragma unroll
        for (int o = 16; o > 0; o >>= 1) {
            float ov = __shfl_down_sync(0xffffffffu, rv, o);
            int   oi = __shfl_down_sync(0xffffffffu, ridx, o);
            int   ol = __shfl_down_sync(0xffffffffu, rlane, o);
            if (ov < rv) { rv = ov; ridx = oi; rlane = ol; }
        }
        ridx  = __shfl_sync(0xffffffffu, ridx, 0);
        rlane = __shfl_sync(0xffffffffu, rlane, 0);
        if (lane == (r & 31)) { if (r < 32) myidx0 = ridx; else myidx1 = ridx; }
        #pragma unroll
        for (int t = 0; t < 7; t++)
            if (lane == rlane && t == ms) cv[t] = FLT_MAX;
    }

    // exact fp32 distances for my candidates
    ((float4*)xs[warp])[lane] = ((const float4*)(x + (size_t)q * DIMS))[lane];
    __syncwarp();
    const float4* x4 = (const float4*)xs[warp];
    float x2v = g_x2[q];

    float myv0, myv1; int lab0, lab1;
    {
        const float4* t4 = (const float4*)(train + (size_t)myidx0 * DIMS);
        float dot = 0.f;
        #pragma unroll 8
        for (int i = 0; i < 32; i++) {
            float4 tv = t4[i], xv = x4[i];
            dot += xv.x*tv.x + xv.y*tv.y + xv.z*tv.z + xv.w*tv.w;
        }
        myv0 = sqrtf(fmaxf(x2v + g_t2[myidx0] - 2.0f * dot, 0.0f));
        lab0 = labels[myidx0];
    }
    {
        const float4* t4 = (const float4*)(train + (size_t)myidx1 * DIMS);
        float dot = 0.f;
        #pragma unroll 8
        for (int i = 0; i < 32; i++) {
            float4 tv = t4[i], xv = x4[i];
            dot += xv.x*tv.x + xv.y*tv.y + xv.z*tv.z + xv.w*tv.w;
        }
        myv1 = (lane < 16) ? sqrtf(fmaxf(x2v + g_t2[myidx1] - 2.0f * dot, 0.0f)) : FLT_MAX;
        lab1 = labels[myidx1];
    }

    // exact top-16 of 48 + weighted vote
    float proba[NC], pz[NC];
    #pragma unroll
    for (int c = 0; c < NC; c++) { proba[c] = 0.f; pz[c] = 0.f; }
    bool anyz = false;

    for (int r = 0; r < KNB; r++) {
        int sel = (myv1 < myv0) ? 1 : 0;
        float rv = sel ? myv1 : myv0;
        int rlab = sel ? lab1 : lab0;
        int rlane = lane, rsel = sel;
        #pragma unroll
        for (int o = 16; o > 0; o >>= 1) {
            float ov = __shfl_down_sync(0xffffffffu, rv, o);
            int   oi = __shfl_down_sync(0xffffffffu, rlab, o);
            int   ol = __shfl_down_sync(0xffffffffu, rlane, o);
            int   os = __shfl_down_sync(0xffffffffu, rsel, o);
            if (ov < rv) { rv = ov; rlab = oi; rlane = ol; rsel = os; }
        }
        rv    = __shfl_sync(0xffffffffu, rv, 0);
        rlab  = __shfl_sync(0xffffffffu, rlab, 0);
        rlane = __shfl_sync(0xffffffffu, rlane, 0);
        rsel  = __shfl_sync(0xffffffffu, rsel, 0);
        if (lane == rlane) { if (rsel) myv1 = FLT_MAX; else myv0 = FLT_MAX; }

        if (rv <= 0.0f) {
            anyz = true;
            #pragma unroll
            for (int c = 0; c < NC; c++) pz[c] += (rlab == c) ? 1.0f : 0.0f;
        } else {
            float w = 1.0f / rv;
            #pragma unroll
            for (int c = 0; c < NC; c++) proba[c] += (rlab == c) ? w : 0.0f;
        }
    }

    if (anyz) {
        #pragma unroll
        for (int c = 0; c < NC; c++) proba[c] = pz[c];
    }
    float ssum = 0.f;
    #pragma unroll
    for (int c = 0; c < NC; c++) ssum += proba[c];
    if (ssum == 0.f) ssum = 1.f;
    float inv = 1.f / ssum;

    int best = 0; float bv = proba[0];
    #pragma unroll
    for (int c = 1; c < NC; c++) if (proba[c] > bv) { bv = proba[c]; best = c; }

    if (lane == 0) {
        if (pred_out)  pred_out[q] = (float)best;
        if (proba_out) {
            #pragma unroll
            for (int c = 0; c < NC; c++) proba_out[q * NC + c] = proba[c] * inv;
        }
    }
}

// -------- launch --------
extern "C" void kernel_launch(void* const* d_in, const int* in_sizes, int n_in,
                              void* d_out, int out_size) {
    const float* x      = (const float*)d_in[0];
    const float* train  = (const float*)d_in[1];
    const int*   labels = (const int*)d_in[2];
    float* out = (float*)d_out;

    float* pred_out  = nullptr;
    float* proba_out = nullptr;
    if (out_size >= NQ * (NC + 1)) { pred_out = out; proba_out = out + NQ; }
    else if (out_size == NQ * NC)  { proba_out = out; }
    else                           { pred_out = out; }

    cudaFuncSetAttribute(knn_kernel, cudaFuncAttributeMaxDynamicSharedMemorySize, SMEM_TOTAL);

    prep_kernel<<<(MTRAIN + NQ + 128 + 7) / 8, 256>>>(x, train);
    knn_kernel<<<dim3(NSPLIT, NQ / QTILE), 256, SMEM_TOTAL>>>();
    finalize_kernel<<<NQ / 8, 256>>>(x, train, labels, pred_out, proba_out);
}